// round 5
// baseline (speedup 1.0000x reference)
#include <cuda_runtime.h>
#include <cstdint>

#define NBATCH 2
#define WW 80
#define NTOK 6400
#define NHEADS 8
#define HD 16
#define ATTN_SCALE 0.25f

// ---------------- scratch (static __device__ — no allocations) ----------------
__device__ float g_Q[(size_t)NBATCH * NHEADS * NTOK * HD];     // (b,h,tok,d)
__device__ float g_K[(size_t)NBATCH * NHEADS * NTOK * HD];
__device__ float g_V[(size_t)NBATCH * NHEADS * NTOK * HD];
__device__ float g_Osum[(size_t)NBATCH * NTOK * 128];          // (b,dest_tok, h*16+d)
__device__ float g_Wc[128 * 128];                              // wproj @ wfinal
__device__ float g_bc[128];                                    // 3*bproj@wfinal + bfinal
__device__ float g_Vc40[64 * 40 * 16];                         // per bh: column sums of V
__device__ float g_Vr40[64 * 40 * 16];                         // per bh: row sums of V

__device__ __forceinline__ void load16(const float* __restrict__ p, float* r) {
#pragma unroll
    for (int i = 0; i < 4; i++) {
        float4 t = ((const float4*)p)[i];
        r[4 * i + 0] = t.x; r[4 * i + 1] = t.y; r[4 * i + 2] = t.z; r[4 * i + 3] = t.w;
    }
}

// ---------------- packed f32x2 helpers (Blackwell FFMA2 — PTX-only path) ----------------
__device__ __forceinline__ uint64_t pack2(float lo, float hi) {
    uint64_t r; asm("mov.b64 %0, {%1, %2};" : "=l"(r) : "f"(lo), "f"(hi)); return r;
}
__device__ __forceinline__ void unpack2(uint64_t v, float& lo, float& hi) {
    asm("mov.b64 {%0, %1}, %2;" : "=f"(lo), "=f"(hi) : "l"(v));
}
__device__ __forceinline__ uint64_t fma2(uint64_t a, uint64_t b, uint64_t c) {
    uint64_t d; asm("fma.rn.f32x2 %0, %1, %2, %3;" : "=l"(d) : "l"(a), "l"(b), "l"(c)); return d;
}
__device__ __forceinline__ uint64_t mul2(uint64_t a, uint64_t b) {
    uint64_t d; asm("mul.rn.f32x2 %0, %1, %2;" : "=l"(d) : "l"(a), "l"(b)); return d;
}

// ---------------- QKV projection: X(12800,128) @ [wq|wkv](128,384) ----------------
__global__ __launch_bounds__(256) void qkv_gemm_kernel(
    const float* __restrict__ X, const float* __restrict__ wq,
    const float* __restrict__ wkv) {
    __shared__ float As[16][64];
    __shared__ float Bs[16][64];
    const int m0 = blockIdx.x * 64;
    const int n0 = blockIdx.y * 64;
    const float* bsrc; int ld;
    if (n0 < 128) { bsrc = wq + n0; ld = 128; }
    else          { bsrc = wkv + (n0 - 128); ld = 256; }
    const int tid = threadIdx.x;
    const int tm = tid >> 4, tn = tid & 15;
    float acc[4][4];
#pragma unroll
    for (int i = 0; i < 4; i++)
#pragma unroll
        for (int j = 0; j < 4; j++) acc[i][j] = 0.f;

    for (int k0 = 0; k0 < 128; k0 += 16) {
        {
            int row = tid >> 2, kp = (tid & 3) << 2;
            float4 av = *(const float4*)&X[(size_t)(m0 + row) * 128 + k0 + kp];
            As[kp + 0][row] = av.x; As[kp + 1][row] = av.y;
            As[kp + 2][row] = av.z; As[kp + 3][row] = av.w;
            int kk = tid >> 4, j4 = (tid & 15) << 2;
            *(float4*)&Bs[kk][j4] = *(const float4*)&bsrc[(size_t)(k0 + kk) * ld + j4];
        }
        __syncthreads();
#pragma unroll
        for (int kk = 0; kk < 16; kk++) {
            float4 a = *(const float4*)&As[kk][tm << 2];
            float4 bv = *(const float4*)&Bs[kk][tn << 2];
            float aa[4] = {a.x, a.y, a.z, a.w};
            float bb[4] = {bv.x, bv.y, bv.z, bv.w};
#pragma unroll
            for (int i = 0; i < 4; i++)
#pragma unroll
                for (int j = 0; j < 4; j++) acc[i][j] = fmaf(aa[i], bb[j], acc[i][j]);
        }
        __syncthreads();
    }
    const int region = n0 >> 7;                 // 0:Q 1:K 2:V
    float* dst = (region == 0) ? g_Q : (region == 1 ? g_K : g_V);
    const int jb = (n0 & 127) + (tn << 2);
    const int h = jb >> 4, dd = jb & 15;
#pragma unroll
    for (int i = 0; i < 4; i++) {
        int t = m0 + (tm << 2) + i;
        int b = t / NTOK, tok = t - b * NTOK;
        float4 v = make_float4(acc[i][0], acc[i][1], acc[i][2], acc[i][3]);
        *(float4*)&dst[((size_t)(b * NHEADS + h) * NTOK + tok) * HD + dd] = v;
    }
}

// ---------------- Wc = wproj @ wfinal ; bc = 3*bproj@wfinal + bfinal ----------------
__global__ void wc_kernel(const float* __restrict__ wproj, const float* __restrict__ wfinal,
                          const float* __restrict__ bproj, const float* __restrict__ bfinal) {
    int i = blockIdx.x, j = threadIdx.x;
    float s = 0.f;
    for (int k = 0; k < 128; k++) s = fmaf(wproj[i * 128 + k], wfinal[k * 128 + j], s);
    g_Wc[i * 128 + j] = s;
    if (i == 0) {
        float sb = 0.f;
        for (int k = 0; k < 128; k++) sb = fmaf(bproj[k], wfinal[k * 128 + j], sb);
        g_bc[j] = 3.f * sb + bfinal[j];
    }
}

// ---------------- V row/col sums for p=40 rel-pos decomposition ----------------
__global__ void vsum40_kernel() {
    const int bh = blockIdx.x;                  // (b*4 + blk)*8 + h
    const int b = bh >> 5, blk = (bh >> 3) & 3, h = bh & 7;
    const int bi = blk >> 1, bj = blk & 1;
    const int tid = threadIdx.x;                // 640
    const int idx = tid >> 4, dd = tid & 15;
    const float* Vb = g_V + (size_t)(b * NHEADS + h) * NTOK * HD;
    float sc = 0.f, sr = 0.f;
    for (int k2 = 0; k2 < 40; k2++) {
        sc += Vb[((bi * 40 + k2) * WW + bj * 40 + idx) * HD + dd];
        sr += Vb[((bi * 40 + idx) * WW + bj * 40 + k2) * HD + dd];
    }
    g_Vc40[bh * 640 + idx * 16 + dd] = sc;
    g_Vr40[bh * 640 + idx * 16 + dd] = sr;
}

// ---------------- attention for p in {4,8}: whole block resident ----------------
// Reference output is NOT un-patchified — flat reshape, so the destination
// token index is patch-major: (bi*NBW + bj)*P*P + r*P + c.
template <int P, int HPC, bool ACCUM>
__global__ __launch_bounds__(P * P * HPC) void attn_small_kernel(
    const float* __restrict__ relw, const float* __restrict__ relh) {
    constexpr int N = P * P;
    constexpr int THREADS = N * HPC;
    constexpr int NBW = WW / P;
    constexpr int NB = NBW * NBW;
    constexpr int HG = NHEADS / HPC;
    __shared__ float Ks[HPC][N][16];
    __shared__ float Vs[HPC][N][16];
    __shared__ float Vc[HPC][P][16];
    __shared__ float Vr[HPC][P][16];
    __shared__ float rwT[16][2 * P];
    __shared__ float rhT[16][2 * P];

    const int cta = blockIdx.x;
    const int hg = cta % HG;
    const int blk = (cta / HG) % NB;
    const int b = cta / (HG * NB);
    const int bi = blk / NBW, bj = blk % NBW;
    const int tid = threadIdx.x;
    const int hh = tid / N;
    const int qi = tid - hh * N;
    const int h = hg * HPC + hh;

    for (int e = tid; e < (2 * P - 1) * 16; e += THREADS) {
        int rr = e >> 4, d = e & 15;
        rwT[d][rr] = relw[e];
        rhT[d][rr] = relh[e];
    }
    for (int e = tid; e < HPC * N * 4; e += THREADS) {
        int hl = e / (N * 4);
        int rem = e - hl * (N * 4);
        int key = rem >> 2, part = (rem & 3) << 2;
        int kr = key / P, kc = key - kr * P;
        int ktok = (bi * P + kr) * WW + bj * P + kc;
        size_t basek = (size_t)(b * NHEADS + hg * HPC + hl) * NTOK;
        *(float4*)&Ks[hl][key][part] = *(const float4*)&g_K[(basek + ktok) * HD + part];
        *(float4*)&Vs[hl][key][part] = *(const float4*)&g_V[(basek + ktok) * HD + part];
    }
    __syncthreads();
    for (int e = tid; e < HPC * P * 16; e += THREADS) {
        int hl = e / (P * 16);
        int rem = e - hl * (P * 16);
        int idx = rem >> 4, dd = rem & 15;
        float sc = 0.f, sr = 0.f;
#pragma unroll
        for (int k2 = 0; k2 < P; k2++) {
            sc += Vs[hl][k2 * P + idx][dd];
            sr += Vs[hl][idx * P + k2][dd];
        }
        Vc[hl][idx][dd] = sc;
        Vr[hl][idx][dd] = sr;
    }
    __syncthreads();

    const int r = qi / P, c = qi - (qi / P) * P;
    const int qtok = (bi * P + r) * WW + bj * P + c;     // spatial (for reading Q)
    const size_t base = (size_t)(b * NHEADS + h) * NTOK;
    float q[16];
    load16(&g_Q[(base + qtok) * HD], q);
    float o[16];
#pragma unroll
    for (int d = 0; d < 16; d++) o[d] = 0.f;
    float ssum = 0.f;

    for (int kk = 0; kk < N; kk++) {
        float kv[16];
        load16(&Ks[hh][kk][0], kv);
        float s = 0.f;
#pragma unroll
        for (int d = 0; d < 16; d++) s = fmaf(q[d], kv[d], s);
        float ew = __expf(s * ATTN_SCALE);
        ssum += ew;
        float vv[16];
        load16(&Vs[hh][kk][0], vv);
#pragma unroll
        for (int d = 0; d < 16; d++) o[d] = fmaf(ew, vv[d], o[d]);
    }
    float inv = 1.f / ssum;
#pragma unroll
    for (int d = 0; d < 16; d++) o[d] *= inv;

    const int cw = P - 1 - c, rw = P - 1 - r;
#pragma unroll 2
    for (int kc = 0; kc < P; kc++) {
        float w = 0.f, wh = 0.f;
#pragma unroll
        for (int d = 0; d < 16; d++) {
            w = fmaf(q[d], rwT[d][kc + cw], w);
            wh = fmaf(q[d], rhT[d][kc + rw], wh);
        }
        float vcv[16], vrv[16];
        load16(&Vc[hh][kc][0], vcv);
        load16(&Vr[hh][kc][0], vrv);
#pragma unroll
        for (int d = 0; d < 16; d++) {
            o[d] = fmaf(w, vcv[d], o[d]);
            o[d] = fmaf(wh, vrv[d], o[d]);
        }
    }
    // patch-major destination (flat reshape in reference)
    const int dtok = (bi * NBW + bj) * N + qi;
    float* dst = g_Osum + ((size_t)b * NTOK + dtok) * 128 + h * HD;
#pragma unroll
    for (int d4 = 0; d4 < 4; d4++) {
        float4 val = make_float4(o[4 * d4], o[4 * d4 + 1], o[4 * d4 + 2], o[4 * d4 + 3]);
        if (ACCUM) {
            float4 cur = *(float4*)&dst[4 * d4];
            val.x += cur.x; val.y += cur.y; val.z += cur.z; val.w += cur.w;
        }
        *(float4*)&dst[4 * d4] = val;
    }
}

// ---------------- attention for p=40 (n=1600): K/V streamed through smem ----------------
// 2 queries per thread; inner math in packed f32x2 (FFMA2) — halves fma-pipe demand.
__global__ __launch_bounds__(160) void attn40_kernel(
    const float* __restrict__ relw, const float* __restrict__ relh) {
    __shared__ float Ks[160][16];
    __shared__ float Vs[160][16];
    __shared__ float rwT[16][80];
    __shared__ float rhT[16][80];
    __shared__ float Vc[40][16];
    __shared__ float Vr[40][16];

    const int bh = blockIdx.x / 5;
    const int qc = blockIdx.x - bh * 5;
    const int b = bh >> 5, blk = (bh >> 3) & 3, h = bh & 7;
    const int bi = blk >> 1, bj = blk & 1;
    const int tid = threadIdx.x;
    const size_t base = (size_t)(b * NHEADS + h) * NTOK;

    for (int e = tid; e < 79 * 16; e += 160) {
        int rr = e >> 4, d = e & 15;
        rwT[d][rr] = relw[e];
        rhT[d][rr] = relh[e];
    }
    for (int e = tid; e < 640; e += 160) {
        ((float*)Vc)[e] = g_Vc40[bh * 640 + e];
        ((float*)Vr)[e] = g_Vr40[bh * 640 + e];
    }

    const int qi0 = qc * 320 + tid;
    const int qi1 = qi0 + 160;
    const int r0 = qi0 / 40, c0 = qi0 - r0 * 40;
    const int r1 = qi1 / 40, c1 = qi1 - r1 * 40;
    // packed q (8 x f32x2 per query)
    uint64_t q0p[8], q1p[8];
#pragma unroll
    for (int i = 0; i < 4; i++) {
        ((float4*)q0p)[i] = ((const float4*)&g_Q[(base + (bi * 40 + r0) * WW + bj * 40 + c0) * HD])[i];
        ((float4*)q1p)[i] = ((const float4*)&g_Q[(base + (bi * 40 + r1) * WW + bj * 40 + c1) * HD])[i];
    }
    uint64_t o0p[8], o1p[8];
#pragma unroll
    for (int i = 0; i < 8; i++) { o0p[i] = 0ull; o1p[i] = 0ull; }
    float ssum0 = 0.f, ssum1 = 0.f;

    for (int t = 0; t < 10; t++) {
        __syncthreads();
#pragma unroll
        for (int l = 0; l < 4; l++) {
            int e = tid + l * 160;
            int key = e >> 2, part = (e & 3) << 2;
            int kidx = t * 160 + key;
            int kr = kidx / 40, kc = kidx - kr * 40;
            int ktok = (bi * 40 + kr) * WW + bj * 40 + kc;
            *(float4*)&Ks[key][part] = *(const float4*)&g_K[(base + ktok) * HD + part];
            *(float4*)&Vs[key][part] = *(const float4*)&g_V[(base + ktok) * HD + part];
        }
        __syncthreads();
#pragma unroll 2
        for (int kk = 0; kk < 160; kk++) {
            uint64_t kv2[8];
#pragma unroll
            for (int i = 0; i < 4; i++) ((float4*)kv2)[i] = ((const float4*)&Ks[kk][0])[i];
            uint64_t s0p = 0ull, s1p = 0ull;
#pragma unroll
            for (int i = 0; i < 8; i++) {
                s0p = fma2(q0p[i], kv2[i], s0p);
                s1p = fma2(q1p[i], kv2[i], s1p);
            }
            float s0a, s0b, s1a, s1b;
            unpack2(s0p, s0a, s0b);
            unpack2(s1p, s1a, s1b);
            float ew0 = __expf((s0a + s0b) * ATTN_SCALE);
            float ew1 = __expf((s1a + s1b) * ATTN_SCALE);
            ssum0 += ew0; ssum1 += ew1;
            uint64_t e0p = pack2(ew0, ew0);
            uint64_t e1p = pack2(ew1, ew1);
            uint64_t vv2[8];
#pragma unroll
            for (int i = 0; i < 4; i++) ((float4*)vv2)[i] = ((const float4*)&Vs[kk][0])[i];
#pragma unroll
            for (int i = 0; i < 8; i++) {
                o0p[i] = fma2(e0p, vv2[i], o0p[i]);
                o1p[i] = fma2(e1p, vv2[i], o1p[i]);
            }
        }
    }
    float inv0 = 1.f / ssum0, inv1 = 1.f / ssum1;
    uint64_t i0p = pack2(inv0, inv0), i1p = pack2(inv1, inv1);
    float o0[16], o1[16];
#pragma unroll
    for (int i = 0; i < 8; i++) {
        uint64_t a = mul2(o0p[i], i0p);
        uint64_t bq = mul2(o1p[i], i1p);
        unpack2(a, o0[2 * i], o0[2 * i + 1]);
        unpack2(bq, o1[2 * i], o1[2 * i + 1]);
    }
    float q0[16], q1[16];
#pragma unroll
    for (int i = 0; i < 8; i++) {
        unpack2(q0p[i], q0[2 * i], q0[2 * i + 1]);
        unpack2(q1p[i], q1[2 * i], q1[2 * i + 1]);
    }

    // rel-pos epilogue per query (40 keys each — minor cost)
    {
        const int cw = 39 - c0, rw = 39 - r0;
#pragma unroll 2
        for (int kc = 0; kc < 40; kc++) {
            float w = 0.f, wh = 0.f;
#pragma unroll
            for (int d = 0; d < 16; d++) {
                w = fmaf(q0[d], rwT[d][kc + cw], w);
                wh = fmaf(q0[d], rhT[d][kc + rw], wh);
            }
            float vcv[16], vrv[16];
            load16(&Vc[kc][0], vcv);
            load16(&Vr[kc][0], vrv);
#pragma unroll
            for (int d = 0; d < 16; d++) {
                o0[d] = fmaf(w, vcv[d], o0[d]);
                o0[d] = fmaf(wh, vrv[d], o0[d]);
            }
        }
    }
    {
        const int cw = 39 - c1, rw = 39 - r1;
#pragma unroll 2
        for (int kc = 0; kc < 40; kc++) {
            float w = 0.f, wh = 0.f;
#pragma unroll
            for (int d = 0; d < 16; d++) {
                w = fmaf(q1[d], rwT[d][kc + cw], w);
                wh = fmaf(q1[d], rhT[d][kc + rw], wh);
            }
            float vcv[16], vrv[16];
            load16(&Vc[kc][0], vcv);
            load16(&Vr[kc][0], vrv);
#pragma unroll
            for (int d = 0; d < 16; d++) {
                o1[d] = fmaf(w, vcv[d], o1[d]);
                o1[d] = fmaf(wh, vrv[d], o1[d]);
            }
        }
    }
    // patch-major destination: (bi*2 + bj)*1600 + qi
    const int pbase = (bi * 2 + bj) * 1600;
    float* dst0 = g_Osum + ((size_t)b * NTOK + pbase + qi0) * 128 + h * HD;
    float* dst1 = g_Osum + ((size_t)b * NTOK + pbase + qi1) * 128 + h * HD;
#pragma unroll
    for (int d4 = 0; d4 < 4; d4++) {
        float4 cur = *(float4*)&dst0[4 * d4];
        cur.x += o0[4 * d4 + 0]; cur.y += o0[4 * d4 + 1];
        cur.z += o0[4 * d4 + 2]; cur.w += o0[4 * d4 + 3];
        *(float4*)&dst0[4 * d4] = cur;
    }
#pragma unroll
    for (int d4 = 0; d4 < 4; d4++) {
        float4 cur = *(float4*)&dst1[4 * d4];
        cur.x += o1[4 * d4 + 0]; cur.y += o1[4 * d4 + 1];
        cur.z += o1[4 * d4 + 2]; cur.w += o1[4 * d4 + 3];
        *(float4*)&dst1[4 * d4] = cur;
    }
}

// ---------------- final: out = Osum @ Wc + bc ----------------
__global__ __launch_bounds__(256) void final_gemm_kernel(float* __restrict__ out) {
    __shared__ float As[16][64];
    __shared__ float Bs[16][64];
    const int m0 = blockIdx.x * 64;
    const int n0 = blockIdx.y * 64;
    const int tid = threadIdx.x;
    const int tm = tid >> 4, tn = tid & 15;
    float acc[4][4];
#pragma unroll
    for (int i = 0; i < 4; i++)
#pragma unroll
        for (int j = 0; j < 4; j++) acc[i][j] = 0.f;

    for (int k0 = 0; k0 < 128; k0 += 16) {
        {
            int row = tid >> 2, kp = (tid & 3) << 2;
            float4 av = *(const float4*)&g_Osum[(size_t)(m0 + row) * 128 + k0 + kp];
            As[kp + 0][row] = av.x; As[kp + 1][row] = av.y;
            As[kp + 2][row] = av.z; As[kp + 3][row] = av.w;
            int kk = tid >> 4, j4 = (tid & 15) << 2;
            *(float4*)&Bs[kk][j4] = *(const float4*)&g_Wc[(size_t)(k0 + kk) * 128 + n0 + j4];
        }
        __syncthreads();
#pragma unroll
        for (int kk = 0; kk < 16; kk++) {
            float4 a = *(const float4*)&As[kk][tm << 2];
            float4 bv = *(const float4*)&Bs[kk][tn << 2];
            float aa[4] = {a.x, a.y, a.z, a.w};
            float bb[4] = {bv.x, bv.y, bv.z, bv.w};
#pragma unroll
            for (int i = 0; i < 4; i++)
#pragma unroll
                for (int j = 0; j < 4; j++) acc[i][j] = fmaf(aa[i], bb[j], acc[i][j]);
        }
        __syncthreads();
    }
    float4 bcv = *(const float4*)&g_bc[n0 + (tn << 2)];
    float bb[4] = {bcv.x, bcv.y, bcv.z, bcv.w};
#pragma unroll
    for (int i = 0; i < 4; i++) {
        int t = m0 + (tm << 2) + i;
        float4 v = make_float4(acc[i][0] + bb[0], acc[i][1] + bb[1],
                               acc[i][2] + bb[2], acc[i][3] + bb[3]);
        *(float4*)&out[(size_t)t * 128 + n0 + (tn << 2)] = v;
    }
}

// ---------------- launcher ----------------
extern "C" void kernel_launch(void* const* d_in, const int* in_sizes, int n_in,
                              void* d_out, int out_size) {
    (void)in_sizes; (void)n_in; (void)out_size;
    const float* x      = (const float*)d_in[0];
    const float* wq     = (const float*)d_in[1];
    const float* wkv    = (const float*)d_in[2];
    const float* wproj  = (const float*)d_in[3];
    const float* bproj  = (const float*)d_in[4];
    const float* wfinal = (const float*)d_in[5];
    const float* bfinal = (const float*)d_in[6];
    const float* rw0 = (const float*)d_in[7];
    const float* rh0 = (const float*)d_in[8];
    const float* rw1 = (const float*)d_in[9];
    const float* rh1 = (const float*)d_in[10];
    const float* rw2 = (const float*)d_in[11];
    const float* rh2 = (const float*)d_in[12];
    float* out = (float*)d_out;

    qkv_gemm_kernel<<<dim3(200, 6), 256>>>(x, wq, wkv);
    wc_kernel<<<128, 128>>>(wproj, wfinal, bproj, bfinal);
    vsum40_kernel<<<64, 640>>>();
    // p=4 STORES (initializes g_Osum: every (token,head) covered exactly once)
    attn_small_kernel<4, 8, false><<<800, 128>>>(rw0, rh0);
    attn_small_kernel<8, 2, true><<<800, 128>>>(rw1, rh1);
    attn40_kernel<<<320, 160>>>(rw2, rh2);
    final_gemm_kernel<<<dim3(200, 2), 256>>>(out);
}

// round 7
// speedup vs baseline: 2.0398x; 2.0398x over previous
#include <cuda_runtime.h>
#include <cstdint>

#define NBATCH 2
#define WW 80
#define NTOK 6400
#define NHEADS 8
#define HD 16
#define ATTN_SCALE 0.25f
#define QK_SCALE (0.25f * 1.4426950408889634f)   // fold softmax scale * log2(e) into Q

// ---------------- scratch (static __device__ — no allocations) ----------------
__device__ float g_Q[(size_t)NBATCH * NHEADS * NTOK * HD];     // (b,h,tok,d)
__device__ float g_K[(size_t)NBATCH * NHEADS * NTOK * HD];
__device__ float g_V[(size_t)NBATCH * NHEADS * NTOK * HD];
__device__ float g_Osum[(size_t)NBATCH * NTOK * 128];          // (b,dest_tok, h*16+d)
__device__ float g_Wc[128 * 128];                              // wproj @ wfinal
__device__ float g_bc[128];                                    // 3*bproj@wfinal + bfinal
__device__ float g_Vc40[64 * 40 * 16];                         // per bh: column sums of V
__device__ float g_Vr40[64 * 40 * 16];                         // per bh: row sums of V

__device__ __forceinline__ void load16(const float* __restrict__ p, float* r) {
#pragma unroll
    for (int i = 0; i < 4; i++) {
        float4 t = ((const float4*)p)[i];
        r[4 * i + 0] = t.x; r[4 * i + 1] = t.y; r[4 * i + 2] = t.z; r[4 * i + 3] = t.w;
    }
}

// pack(lo, hi): lo -> low 16 bits (first element), hi -> high 16 bits
__device__ __forceinline__ uint32_t bf16x2(float lo, float hi) {
    uint32_t r;
    asm("cvt.rn.bf16x2.f32 %0, %1, %2;" : "=r"(r) : "f"(hi), "f"(lo));
    return r;
}
__device__ __forceinline__ float ex2f(float x) {
    float r; asm("ex2.approx.f32 %0, %1;" : "=f"(r) : "f"(x)); return r;
}
__device__ __forceinline__ void mma_bf16(
    float& c0, float& c1, float& c2, float& c3,
    uint32_t a0, uint32_t a1, uint32_t a2, uint32_t a3,
    uint32_t b0, uint32_t b1) {
    asm("mma.sync.aligned.m16n8k16.row.col.f32.bf16.bf16.f32 "
        "{%0,%1,%2,%3}, {%4,%5,%6,%7}, {%8,%9}, {%0,%1,%2,%3};"
        : "+f"(c0), "+f"(c1), "+f"(c2), "+f"(c3)
        : "r"(a0), "r"(a1), "r"(a2), "r"(a3), "r"(b0), "r"(b1));
}

// ---------------- QKV projection: X(12800,128) @ [wq|wkv](128,384) ----------------
__global__ __launch_bounds__(256) void qkv_gemm_kernel(
    const float* __restrict__ X, const float* __restrict__ wq,
    const float* __restrict__ wkv) {
    __shared__ float As[16][64];
    __shared__ float Bs[16][64];
    const int m0 = blockIdx.x * 64;
    const int n0 = blockIdx.y * 64;
    const float* bsrc; int ld;
    if (n0 < 128) { bsrc = wq + n0; ld = 128; }
    else          { bsrc = wkv + (n0 - 128); ld = 256; }
    const int tid = threadIdx.x;
    const int tm = tid >> 4, tn = tid & 15;
    float acc[4][4];
#pragma unroll
    for (int i = 0; i < 4; i++)
#pragma unroll
        for (int j = 0; j < 4; j++) acc[i][j] = 0.f;

    for (int k0 = 0; k0 < 128; k0 += 16) {
        {
            int row = tid >> 2, kp = (tid & 3) << 2;
            float4 av = *(const float4*)&X[(size_t)(m0 + row) * 128 + k0 + kp];
            As[kp + 0][row] = av.x; As[kp + 1][row] = av.y;
            As[kp + 2][row] = av.z; As[kp + 3][row] = av.w;
            int kk = tid >> 4, j4 = (tid & 15) << 2;
            *(float4*)&Bs[kk][j4] = *(const float4*)&bsrc[(size_t)(k0 + kk) * ld + j4];
        }
        __syncthreads();
#pragma unroll
        for (int kk = 0; kk < 16; kk++) {
            float4 a = *(const float4*)&As[kk][tm << 2];
            float4 bv = *(const float4*)&Bs[kk][tn << 2];
            float aa[4] = {a.x, a.y, a.z, a.w};
            float bb[4] = {bv.x, bv.y, bv.z, bv.w};
#pragma unroll
            for (int i = 0; i < 4; i++)
#pragma unroll
                for (int j = 0; j < 4; j++) acc[i][j] = fmaf(aa[i], bb[j], acc[i][j]);
        }
        __syncthreads();
    }
    const int region = n0 >> 7;                 // 0:Q 1:K 2:V
    float* dst = (region == 0) ? g_Q : (region == 1 ? g_K : g_V);
    const int jb = (n0 & 127) + (tn << 2);
    const int h = jb >> 4, dd = jb & 15;
#pragma unroll
    for (int i = 0; i < 4; i++) {
        int t = m0 + (tm << 2) + i;
        int b = t / NTOK, tok = t - b * NTOK;
        float4 v = make_float4(acc[i][0], acc[i][1], acc[i][2], acc[i][3]);
        *(float4*)&dst[((size_t)(b * NHEADS + h) * NTOK + tok) * HD + dd] = v;
    }
}

// ---------------- Wc = wproj @ wfinal ; bc = 3*bproj@wfinal + bfinal ----------------
__global__ void wc_kernel(const float* __restrict__ wproj, const float* __restrict__ wfinal,
                          const float* __restrict__ bproj, const float* __restrict__ bfinal) {
    int i = blockIdx.x, j = threadIdx.x;
    float s = 0.f;
    for (int k = 0; k < 128; k++) s = fmaf(wproj[i * 128 + k], wfinal[k * 128 + j], s);
    g_Wc[i * 128 + j] = s;
    if (i == 0) {
        float sb = 0.f;
        for (int k = 0; k < 128; k++) sb = fmaf(bproj[k], wfinal[k * 128 + j], sb);
        g_bc[j] = 3.f * sb + bfinal[j];
    }
}

// ---------------- V row/col sums for p=40 rel-pos decomposition ----------------
__global__ void vsum40_kernel() {
    const int bh = blockIdx.x;                  // (b*4 + blk)*8 + h
    const int b = bh >> 5, blk = (bh >> 3) & 3, h = bh & 7;
    const int bi = blk >> 1, bj = blk & 1;
    const int tid = threadIdx.x;                // 640
    const int idx = tid >> 4, dd = tid & 15;
    const float* Vb = g_V + (size_t)(b * NHEADS + h) * NTOK * HD;
    float sc = 0.f, sr = 0.f;
    for (int k2 = 0; k2 < 40; k2++) {
        sc += Vb[((bi * 40 + k2) * WW + bj * 40 + idx) * HD + dd];
        sr += Vb[((bi * 40 + idx) * WW + bj * 40 + k2) * HD + dd];
    }
    g_Vc40[bh * 640 + idx * 16 + dd] = sc;
    g_Vr40[bh * 640 + idx * 16 + dd] = sr;
}

// ---------------- attention for p in {4,8}: whole block resident ----------------
// Reference output is NOT un-patchified — flat reshape, so the destination
// token index is patch-major: (bi*NBW + bj)*P*P + r*P + c.
template <int P, int HPC, bool ACCUM>
__global__ __launch_bounds__(P * P * HPC) void attn_small_kernel(
    const float* __restrict__ relw, const float* __restrict__ relh) {
    constexpr int N = P * P;
    constexpr int THREADS = N * HPC;
    constexpr int NBW = WW / P;
    constexpr int NB = NBW * NBW;
    constexpr int HG = NHEADS / HPC;
    __shared__ float Ks[HPC][N][16];
    __shared__ float Vs[HPC][N][16];
    __shared__ float Vc[HPC][P][16];
    __shared__ float Vr[HPC][P][16];
    __shared__ float rwT[16][2 * P];
    __shared__ float rhT[16][2 * P];

    const int cta = blockIdx.x;
    const int hg = cta % HG;
    const int blk = (cta / HG) % NB;
    const int b = cta / (HG * NB);
    const int bi = blk / NBW, bj = blk % NBW;
    const int tid = threadIdx.x;
    const int hh = tid / N;
    const int qi = tid - hh * N;
    const int h = hg * HPC + hh;

    for (int e = tid; e < (2 * P - 1) * 16; e += THREADS) {
        int rr = e >> 4, d = e & 15;
        rwT[d][rr] = relw[e];
        rhT[d][rr] = relh[e];
    }
    for (int e = tid; e < HPC * N * 4; e += THREADS) {
        int hl = e / (N * 4);
        int rem = e - hl * (N * 4);
        int key = rem >> 2, part = (rem & 3) << 2;
        int kr = key / P, kc = key - kr * P;
        int ktok = (bi * P + kr) * WW + bj * P + kc;
        size_t basek = (size_t)(b * NHEADS + hg * HPC + hl) * NTOK;
        *(float4*)&Ks[hl][key][part] = *(const float4*)&g_K[(basek + ktok) * HD + part];
        *(float4*)&Vs[hl][key][part] = *(const float4*)&g_V[(basek + ktok) * HD + part];
    }
    __syncthreads();
    for (int e = tid; e < HPC * P * 16; e += THREADS) {
        int hl = e / (P * 16);
        int rem = e - hl * (P * 16);
        int idx = rem >> 4, dd = rem & 15;
        float sc = 0.f, sr = 0.f;
#pragma unroll
        for (int k2 = 0; k2 < P; k2++) {
            sc += Vs[hl][k2 * P + idx][dd];
            sr += Vs[hl][idx * P + k2][dd];
        }
        Vc[hl][idx][dd] = sc;
        Vr[hl][idx][dd] = sr;
    }
    __syncthreads();

    const int r = qi / P, c = qi - (qi / P) * P;
    const int qtok = (bi * P + r) * WW + bj * P + c;     // spatial (for reading Q)
    const size_t base = (size_t)(b * NHEADS + h) * NTOK;
    float q[16];
    load16(&g_Q[(base + qtok) * HD], q);
    float o[16];
#pragma unroll
    for (int d = 0; d < 16; d++) o[d] = 0.f;
    float ssum = 0.f;

    for (int kk = 0; kk < N; kk++) {
        float kv[16];
        load16(&Ks[hh][kk][0], kv);
        float s = 0.f;
#pragma unroll
        for (int d = 0; d < 16; d++) s = fmaf(q[d], kv[d], s);
        float ew = __expf(s * ATTN_SCALE);
        ssum += ew;
        float vv[16];
        load16(&Vs[hh][kk][0], vv);
#pragma unroll
        for (int d = 0; d < 16; d++) o[d] = fmaf(ew, vv[d], o[d]);
    }
    float inv = 1.f / ssum;
#pragma unroll
    for (int d = 0; d < 16; d++) o[d] *= inv;

    const int cw = P - 1 - c, rw = P - 1 - r;
#pragma unroll 2
    for (int kc = 0; kc < P; kc++) {
        float w = 0.f, wh = 0.f;
#pragma unroll
        for (int d = 0; d < 16; d++) {
            w = fmaf(q[d], rwT[d][kc + cw], w);
            wh = fmaf(q[d], rhT[d][kc + rw], wh);
        }
        float vcv[16], vrv[16];
        load16(&Vc[hh][kc][0], vcv);
        load16(&Vr[hh][kc][0], vrv);
#pragma unroll
        for (int d = 0; d < 16; d++) {
            o[d] = fmaf(w, vcv[d], o[d]);
            o[d] = fmaf(wh, vrv[d], o[d]);
        }
    }
    // patch-major destination (flat reshape in reference)
    const int dtok = (bi * NBW + bj) * N + qi;
    float* dst = g_Osum + ((size_t)b * NTOK + dtok) * 128 + h * HD;
#pragma unroll
    for (int d4 = 0; d4 < 4; d4++) {
        float4 val = make_float4(o[4 * d4], o[4 * d4 + 1], o[4 * d4 + 2], o[4 * d4 + 3]);
        if (ACCUM) {
            float4 cur = *(float4*)&dst[4 * d4];
            val.x += cur.x; val.y += cur.y; val.z += cur.z; val.w += cur.w;
        }
        *(float4*)&dst[4 * d4] = val;
    }
}

// ---------------- attention for p=40 via mma.sync bf16 (flash style) ----------------
// 64 block-heads x 10 CTAs; CTA = 320 thr = 10 warps; warp = 16 queries.
// Softmax part in bf16 tensor cores (tiny vs fp32-exact rel-pos part -> safe).
__global__ __launch_bounds__(320) void attn40_kernel(
    const float* __restrict__ relw, const float* __restrict__ relh) {
    __shared__ __align__(16) uint32_t KsU[512];       // [64 keys][8 d-pairs] bf16x2
    __shared__ __align__(16) uint32_t VtU[16 * 36];   // [16 d][32 key-pairs], stride 36 u32
    __shared__ float Os[160][17];                     // softmax output (padded)
    __shared__ float rw[79 * 16], rh[79 * 16];        // rel tables [idx][d]
    __shared__ float Vc[40][16], Vr[40][16];

    const int bh = blockIdx.x / 10;
    const int qc = blockIdx.x - bh * 10;
    const int b = bh >> 5, blk = (bh >> 3) & 3, h = bh & 7;
    const int bi = blk >> 1, bj = blk & 1;
    const int tid = threadIdx.x;
    const size_t base = (size_t)(b * NHEADS + h) * NTOK;

    for (int e = tid; e < 79 * 16; e += 320) { rw[e] = relw[e]; rh[e] = relh[e]; }
    for (int e = tid; e < 640; e += 320) {
        ((float*)Vc)[e] = g_Vc40[bh * 640 + e];
        ((float*)Vr)[e] = g_Vr40[bh * 640 + e];
    }

    const int wid = tid >> 5, lane = tid & 31;
    const int lr = lane >> 2, lc = lane & 3;
    // ---- Q fragment (scaled by QK_SCALE; exact power-of-two * log2e const) ----
    uint32_t qa0, qa1, qa2, qa3;
    {
        int qia = qc * 160 + wid * 16 + lr;
        int qib = qia + 8;
        int ra = qia / 40, ca = qia - ra * 40;
        int rb = qib / 40, cb = qib - rb * 40;
        const float* qpa = &g_Q[(base + (bi * 40 + ra) * WW + bj * 40 + ca) * HD];
        const float* qpb = &g_Q[(base + (bi * 40 + rb) * WW + bj * 40 + cb) * HD];
        float2 f;
        f = *(const float2*)&qpa[2 * lc];     qa0 = bf16x2(f.x * QK_SCALE, f.y * QK_SCALE);
        f = *(const float2*)&qpb[2 * lc];     qa1 = bf16x2(f.x * QK_SCALE, f.y * QK_SCALE);
        f = *(const float2*)&qpa[2 * lc + 8]; qa2 = bf16x2(f.x * QK_SCALE, f.y * QK_SCALE);
        f = *(const float2*)&qpb[2 * lc + 8]; qa3 = bf16x2(f.x * QK_SCALE, f.y * QK_SCALE);
    }
    float oc0[4] = {0.f, 0.f, 0.f, 0.f};
    float oc1[4] = {0.f, 0.f, 0.f, 0.f};
    float rsum0 = 0.f, rsum1 = 0.f;

    for (int t = 0; t < 25; t++) {
        __syncthreads();
        // K tile: 64 keys x 16d as bf16x2
        for (int e = tid; e < 512; e += 320) {
            int key = e >> 3, dp = e & 7;
            int kidx = t * 64 + key;
            int kr = kidx / 40, kc2 = kidx - kr * 40;
            float2 f = *(const float2*)&g_K[(base + (bi * 40 + kr) * WW + bj * 40 + kc2) * HD + 2 * dp];
            KsU[e] = bf16x2(f.x, f.y);
        }
        // V tile transposed: VtU[d][key-pair]
        for (int e = tid; e < 512; e += 320) {
            int d = e >> 5, k2 = e & 31;
            int kidx = t * 64 + 2 * k2;            // even -> pair never crosses a row of 40
            int kr = kidx / 40, kc2 = kidx - kr * 40;
            size_t tok = base + (bi * 40 + kr) * WW + bj * 40 + kc2;
            float lo = g_V[tok * HD + d];
            float hi = g_V[(tok + 1) * HD + d];
            VtU[d * 36 + k2] = bf16x2(lo, hi);
        }
        __syncthreads();

        uint32_t p[8][2];
#pragma unroll
        for (int g = 0; g < 8; g++) {
            float c0 = 0.f, c1 = 0.f, c2 = 0.f, c3 = 0.f;
            uint32_t kb0 = KsU[(8 * g + lr) * 8 + lc];
            uint32_t kb1 = KsU[(8 * g + lr) * 8 + lc + 4];
            mma_bf16(c0, c1, c2, c3, qa0, qa1, qa2, qa3, kb0, kb1);
            float e0 = ex2f(c0), e1 = ex2f(c1), e2 = ex2f(c2), e3 = ex2f(c3);
            rsum0 += e0 + e1;
            rsum1 += e2 + e3;
            p[g][0] = bf16x2(e0, e1);
            p[g][1] = bf16x2(e2, e3);
        }
#pragma unroll
        for (int gp = 0; gp < 4; gp++) {
            uint32_t a0 = p[2 * gp][0], a1 = p[2 * gp][1];
            uint32_t a2 = p[2 * gp + 1][0], a3 = p[2 * gp + 1][1];
            uint32_t vb0 = VtU[lr * 36 + 8 * gp + lc];
            uint32_t vb1 = VtU[lr * 36 + 8 * gp + lc + 4];
            mma_bf16(oc0[0], oc0[1], oc0[2], oc0[3], a0, a1, a2, a3, vb0, vb1);
            vb0 = VtU[(8 + lr) * 36 + 8 * gp + lc];
            vb1 = VtU[(8 + lr) * 36 + 8 * gp + lc + 4];
            mma_bf16(oc1[0], oc1[1], oc1[2], oc1[3], a0, a1, a2, a3, vb0, vb1);
        }
    }
    // quad reduce row sums (lanes 4k..4k+3 share rows)
    rsum0 += __shfl_xor_sync(0xffffffffu, rsum0, 1);
    rsum0 += __shfl_xor_sync(0xffffffffu, rsum0, 2);
    rsum1 += __shfl_xor_sync(0xffffffffu, rsum1, 1);
    rsum1 += __shfl_xor_sync(0xffffffffu, rsum1, 2);
    float inv0 = 1.f / rsum0, inv1 = 1.f / rsum1;
    {
        int ql = wid * 16;
        Os[ql + lr][2 * lc]         = oc0[0] * inv0;
        Os[ql + lr][2 * lc + 1]     = oc0[1] * inv0;
        Os[ql + lr + 8][2 * lc]     = oc0[2] * inv1;
        Os[ql + lr + 8][2 * lc + 1] = oc0[3] * inv1;
        Os[ql + lr][2 * lc + 8]     = oc1[0] * inv0;
        Os[ql + lr][2 * lc + 9]     = oc1[1] * inv0;
        Os[ql + lr + 8][2 * lc + 8] = oc1[2] * inv1;
        Os[ql + lr + 8][2 * lc + 9] = oc1[3] * inv1;
    }
    __syncthreads();

    // ---- fp32 rel-pos epilogue: 2 threads per query (half=0 -> w, half=1 -> wh) ----
    const int qloc = tid >> 1, half = tid & 1;
    const int qi = qc * 160 + qloc;
    const int r = qi / 40, c = qi - r * 40;
    float q[16];
    load16(&g_Q[(base + (bi * 40 + r) * WW + bj * 40 + c) * HD], q);
    float o[8] = {0.f, 0.f, 0.f, 0.f, 0.f, 0.f, 0.f, 0.f};
    const int off = half ? (39 - r) : (39 - c);
    const float* tbl = half ? rh : rw;
#pragma unroll 2
    for (int kc = 0; kc < 40; kc++) {
        const float* tp = &tbl[(kc + off) * 16];
        float mine = 0.f;
#pragma unroll
        for (int d = 0; d < 16; d++) mine = fmaf(q[d], tp[d], mine);
        float other = __shfl_xor_sync(0xffffffffu, mine, 1);
        float w  = half ? other : mine;
        float wh = half ? mine  : other;
#pragma unroll
        for (int j = 0; j < 8; j++)
            o[j] = fmaf(w, Vc[kc][half * 8 + j], fmaf(wh, Vr[kc][half * 8 + j], o[j]));
    }
    const int pbase = (bi * 2 + bj) * 1600;
    float* dst = &g_Osum[((size_t)b * NTOK + pbase + qi) * 128 + h * HD + half * 8];
#pragma unroll
    for (int j4 = 0; j4 < 2; j4++) {
        float4 cur = *(float4*)&dst[4 * j4];
        cur.x += o[4 * j4 + 0] + Os[qloc][half * 8 + 4 * j4 + 0];
        cur.y += o[4 * j4 + 1] + Os[qloc][half * 8 + 4 * j4 + 1];
        cur.z += o[4 * j4 + 2] + Os[qloc][half * 8 + 4 * j4 + 2];
        cur.w += o[4 * j4 + 3] + Os[qloc][half * 8 + 4 * j4 + 3];
        *(float4*)&dst[4 * j4] = cur;
    }
}

// ---------------- final: out = Osum @ Wc + bc ----------------
__global__ __launch_bounds__(256) void final_gemm_kernel(float* __restrict__ out) {
    __shared__ float As[16][64];
    __shared__ float Bs[16][64];
    const int m0 = blockIdx.x * 64;
    const int n0 = blockIdx.y * 64;
    const int tid = threadIdx.x;
    const int tm = tid >> 4, tn = tid & 15;
    float acc[4][4];
#pragma unroll
    for (int i = 0; i < 4; i++)
#pragma unroll
        for (int j = 0; j < 4; j++) acc[i][j] = 0.f;

    for (int k0 = 0; k0 < 128; k0 += 16) {
        {
            int row = tid >> 2, kp = (tid & 3) << 2;
            float4 av = *(const float4*)&g_Osum[(size_t)(m0 + row) * 128 + k0 + kp];
            As[kp + 0][row] = av.x; As[kp + 1][row] = av.y;
            As[kp + 2][row] = av.z; As[kp + 3][row] = av.w;
            int kk = tid >> 4, j4 = (tid & 15) << 2;
            *(float4*)&Bs[kk][j4] = *(const float4*)&g_Wc[(size_t)(k0 + kk) * 128 + n0 + j4];
        }
        __syncthreads();
#pragma unroll
        for (int kk = 0; kk < 16; kk++) {
            float4 a = *(const float4*)&As[kk][tm << 2];
            float4 bv = *(const float4*)&Bs[kk][tn << 2];
            float aa[4] = {a.x, a.y, a.z, a.w};
            float bb[4] = {bv.x, bv.y, bv.z, bv.w};
#pragma unroll
            for (int i = 0; i < 4; i++)
#pragma unroll
                for (int j = 0; j < 4; j++) acc[i][j] = fmaf(aa[i], bb[j], acc[i][j]);
        }
        __syncthreads();
    }
    float4 bcv = *(const float4*)&g_bc[n0 + (tn << 2)];
    float bb[4] = {bcv.x, bcv.y, bcv.z, bcv.w};
#pragma unroll
    for (int i = 0; i < 4; i++) {
        int t = m0 + (tm << 2) + i;
        float4 v = make_float4(acc[i][0] + bb[0], acc[i][1] + bb[1],
                               acc[i][2] + bb[2], acc[i][3] + bb[3]);
        *(float4*)&out[(size_t)t * 128 + n0 + (tn << 2)] = v;
    }
}

// ---------------- launcher ----------------
extern "C" void kernel_launch(void* const* d_in, const int* in_sizes, int n_in,
                              void* d_out, int out_size) {
    (void)in_sizes; (void)n_in; (void)out_size;
    const float* x      = (const float*)d_in[0];
    const float* wq     = (const float*)d_in[1];
    const float* wkv    = (const float*)d_in[2];
    const float* wproj  = (const float*)d_in[3];
    const float* bproj  = (const float*)d_in[4];
    const float* wfinal = (const float*)d_in[5];
    const float* bfinal = (const float*)d_in[6];
    const float* rw0 = (const float*)d_in[7];
    const float* rh0 = (const float*)d_in[8];
    const float* rw1 = (const float*)d_in[9];
    const float* rh1 = (const float*)d_in[10];
    const float* rw2 = (const float*)d_in[11];
    const float* rh2 = (const float*)d_in[12];
    float* out = (float*)d_out;

    qkv_gemm_kernel<<<dim3(200, 6), 256>>>(x, wq, wkv);
    wc_kernel<<<128, 128>>>(wproj, wfinal, bproj, bfinal);
    vsum40_kernel<<<64, 640>>>();
    // p=4 STORES (initializes g_Osum: every (token,head) covered exactly once)
    attn_small_kernel<4, 8, false><<<800, 128>>>(rw0, rh0);
    attn_small_kernel<8, 2, true><<<800, 128>>>(rw1, rh1);
    attn40_kernel<<<640, 320>>>(rw2, rh2);
    final_gemm_kernel<<<dim3(200, 2), 256>>>(out);
}

// round 8
// speedup vs baseline: 2.1537x; 1.0558x over previous
#include <cuda_runtime.h>
#include <cstdint>

#define NBATCH 2
#define WW 80
#define NTOK 6400
#define NHEADS 8
#define HD 16
#define ATTN_SCALE 0.25f
#define QK_SCALE (0.25f * 1.4426950408889634f)   // fold softmax scale * log2(e) into Q

// ---------------- scratch (static __device__ — no allocations) ----------------
__device__ float g_Q[(size_t)NBATCH * NHEADS * NTOK * HD];     // (b,h,tok,d)
__device__ float g_K[(size_t)NBATCH * NHEADS * NTOK * HD];
__device__ float g_V[(size_t)NBATCH * NHEADS * NTOK * HD];
__device__ float g_Osum[(size_t)NBATCH * NTOK * 128];          // (b,dest_tok, h*16+d)
__device__ float g_Wc[128 * 128];                              // wproj @ wfinal
__device__ float g_bc[128];                                    // 3*bproj@wfinal + bfinal
__device__ float g_Vc40[64 * 40 * 16];                         // per bh: column sums of V
__device__ float g_Vr40[64 * 40 * 16];                         // per bh: row sums of V

__device__ __forceinline__ void load16(const float* __restrict__ p, float* r) {
#pragma unroll
    for (int i = 0; i < 4; i++) {
        float4 t = ((const float4*)p)[i];
        r[4 * i + 0] = t.x; r[4 * i + 1] = t.y; r[4 * i + 2] = t.z; r[4 * i + 3] = t.w;
    }
}

// pack(lo, hi): lo -> low 16 bits (first element), hi -> high 16 bits
__device__ __forceinline__ uint32_t bf16x2(float lo, float hi) {
    uint32_t r;
    asm("cvt.rn.bf16x2.f32 %0, %1, %2;" : "=r"(r) : "f"(hi), "f"(lo));
    return r;
}
__device__ __forceinline__ float ex2f(float x) {
    float r; asm("ex2.approx.f32 %0, %1;" : "=f"(r) : "f"(x)); return r;
}
__device__ __forceinline__ void mma_bf16(
    float& c0, float& c1, float& c2, float& c3,
    uint32_t a0, uint32_t a1, uint32_t a2, uint32_t a3,
    uint32_t b0, uint32_t b1) {
    asm("mma.sync.aligned.m16n8k16.row.col.f32.bf16.bf16.f32 "
        "{%0,%1,%2,%3}, {%4,%5,%6,%7}, {%8,%9}, {%0,%1,%2,%3};"
        : "+f"(c0), "+f"(c1), "+f"(c2), "+f"(c3)
        : "r"(a0), "r"(a1), "r"(a2), "r"(a3), "r"(b0), "r"(b1));
}
// split a pair of fp32 into bf16x2 hi and bf16x2 lo (3-term split precision)
__device__ __forceinline__ void split_pair(float a0, float a1, uint32_t& hi, uint32_t& lo) {
    hi = bf16x2(a0, a1);
    float h0 = __uint_as_float(hi << 16);
    float h1 = __uint_as_float(hi & 0xffff0000u);
    lo = bf16x2(a0 - h0, a1 - h1);
}

// ---------------- QKV projection via bf16x3 mma: X(12800,128) @ [wq|wkv](128,384) ----------------
// grid (100, 6), 256 threads (8 warps). M-tile 128, N-tile 64, K chunk 16 (one mma depth).
__global__ __launch_bounds__(256) void qkv_mma_kernel(
    const float* __restrict__ X, const float* __restrict__ wq,
    const float* __restrict__ wkv) {
    __shared__ uint32_t AsH[128][9], AsL[128][9];   // [row][k-pair], pad 9
    __shared__ uint32_t BsH[64][9], BsL[64][9];     // [n][k-pair]
    const int m0 = blockIdx.x * 128;
    const int n0 = blockIdx.y * 64;
    const float* bsrc; int ld;
    if (n0 < 128) { bsrc = wq + n0; ld = 128; }
    else          { bsrc = wkv + (n0 - 128); ld = 256; }
    const int tid = threadIdx.x;
    const int wid = tid >> 5, lane = tid & 31;
    const int lr = lane >> 2, lc = lane & 3;
    float c[8][4];
#pragma unroll
    for (int j = 0; j < 8; j++)
#pragma unroll
        for (int i = 0; i < 4; i++) c[j][i] = 0.f;

    for (int kc = 0; kc < 8; kc++) {
        __syncthreads();
        {   // A chunk: 128 rows x 16 k
            int row = tid >> 1, hf = tid & 1;
            const float* src = &X[(size_t)(m0 + row) * 128 + kc * 16 + hf * 8];
            float4 f0 = *(const float4*)src;
            float4 f1 = *(const float4*)(src + 4);
            uint32_t h, l;
            split_pair(f0.x, f0.y, h, l); AsH[row][hf * 4 + 0] = h; AsL[row][hf * 4 + 0] = l;
            split_pair(f0.z, f0.w, h, l); AsH[row][hf * 4 + 1] = h; AsL[row][hf * 4 + 1] = l;
            split_pair(f1.x, f1.y, h, l); AsH[row][hf * 4 + 2] = h; AsL[row][hf * 4 + 2] = l;
            split_pair(f1.z, f1.w, h, l); AsH[row][hf * 4 + 3] = h; AsL[row][hf * 4 + 3] = l;
        }
#pragma unroll
        for (int ee = 0; ee < 2; ee++) {  // B chunk: 16 k x 64 n
            int e = tid + ee * 256;
            int n = e & 63, kp = e >> 6;
            float b0 = bsrc[(size_t)(kc * 16 + 2 * kp) * ld + n];
            float b1 = bsrc[(size_t)(kc * 16 + 2 * kp + 1) * ld + n];
            uint32_t h, l; split_pair(b0, b1, h, l);
            BsH[n][kp] = h; BsL[n][kp] = l;
        }
        __syncthreads();
        const int rbase = wid * 16;
        uint32_t aH0 = AsH[rbase + lr][lc],     aH1 = AsH[rbase + lr + 8][lc];
        uint32_t aH2 = AsH[rbase + lr][lc + 4], aH3 = AsH[rbase + lr + 8][lc + 4];
        uint32_t aL0 = AsL[rbase + lr][lc],     aL1 = AsL[rbase + lr + 8][lc];
        uint32_t aL2 = AsL[rbase + lr][lc + 4], aL3 = AsL[rbase + lr + 8][lc + 4];
#pragma unroll
        for (int j = 0; j < 8; j++) {
            uint32_t bH0 = BsH[8 * j + lr][lc], bH1 = BsH[8 * j + lr][lc + 4];
            uint32_t bL0 = BsL[8 * j + lr][lc], bL1 = BsL[8 * j + lr][lc + 4];
            mma_bf16(c[j][0], c[j][1], c[j][2], c[j][3], aH0, aH1, aH2, aH3, bH0, bH1);
            mma_bf16(c[j][0], c[j][1], c[j][2], c[j][3], aL0, aL1, aL2, aL3, bH0, bH1);
            mma_bf16(c[j][0], c[j][1], c[j][2], c[j][3], aH0, aH1, aH2, aH3, bL0, bL1);
        }
    }
    const int region = n0 >> 7;                 // 0:Q 1:K 2:V
    float* dst = (region == 0) ? g_Q : (region == 1 ? g_K : g_V);
#pragma unroll
    for (int j = 0; j < 8; j++) {
        int jb = (n0 & 127) + 8 * j + 2 * lc;
        int h = jb >> 4, dd = jb & 15;
        int t0 = m0 + wid * 16 + lr;
        int b0i = t0 / NTOK, tok0 = t0 - b0i * NTOK;
        *(float2*)&dst[((size_t)(b0i * NHEADS + h) * NTOK + tok0) * HD + dd] =
            make_float2(c[j][0], c[j][1]);
        int t1 = t0 + 8;
        int b1i = t1 / NTOK, tok1 = t1 - b1i * NTOK;
        *(float2*)&dst[((size_t)(b1i * NHEADS + h) * NTOK + tok1) * HD + dd] =
            make_float2(c[j][2], c[j][3]);
    }
}

// ---------------- Wc = wproj @ wfinal ; bc = 3*bproj@wfinal + bfinal ----------------
__global__ void wc_kernel(const float* __restrict__ wproj, const float* __restrict__ wfinal,
                          const float* __restrict__ bproj, const float* __restrict__ bfinal) {
    int i = blockIdx.x, j = threadIdx.x;
    float s = 0.f;
    for (int k = 0; k < 128; k++) s = fmaf(wproj[i * 128 + k], wfinal[k * 128 + j], s);
    g_Wc[i * 128 + j] = s;
    if (i == 0) {
        float sb = 0.f;
        for (int k = 0; k < 128; k++) sb = fmaf(bproj[k], wfinal[k * 128 + j], sb);
        g_bc[j] = 3.f * sb + bfinal[j];
    }
}

// ---------------- V row/col sums for p=40 rel-pos decomposition ----------------
__global__ void vsum40_kernel() {
    const int bh = blockIdx.x;                  // (b*4 + blk)*8 + h
    const int b = bh >> 5, blk = (bh >> 3) & 3, h = bh & 7;
    const int bi = blk >> 1, bj = blk & 1;
    const int tid = threadIdx.x;                // 640
    const int idx = tid >> 4, dd = tid & 15;
    const float* Vb = g_V + (size_t)(b * NHEADS + h) * NTOK * HD;
    float sc = 0.f, sr = 0.f;
    for (int k2 = 0; k2 < 40; k2++) {
        sc += Vb[((bi * 40 + k2) * WW + bj * 40 + idx) * HD + dd];
        sr += Vb[((bi * 40 + idx) * WW + bj * 40 + k2) * HD + dd];
    }
    g_Vc40[bh * 640 + idx * 16 + dd] = sc;
    g_Vr40[bh * 640 + idx * 16 + dd] = sr;
}

// ---------------- attention for p in {4,8}: whole block resident ----------------
// Reference output is NOT un-patchified — flat reshape, so the destination
// token index is patch-major: (bi*NBW + bj)*P*P + r*P + c.
template <int P, int HPC, bool ACCUM>
__global__ __launch_bounds__(P * P * HPC) void attn_small_kernel(
    const float* __restrict__ relw, const float* __restrict__ relh) {
    constexpr int N = P * P;
    constexpr int THREADS = N * HPC;
    constexpr int NBW = WW / P;
    constexpr int NB = NBW * NBW;
    constexpr int HG = NHEADS / HPC;
    __shared__ float Ks[HPC][N][16];
    __shared__ float Vs[HPC][N][16];
    __shared__ float Vc[HPC][P][16];
    __shared__ float Vr[HPC][P][16];
    __shared__ float rwT[16][2 * P];
    __shared__ float rhT[16][2 * P];

    const int cta = blockIdx.x;
    const int hg = cta % HG;
    const int blk = (cta / HG) % NB;
    const int b = cta / (HG * NB);
    const int bi = blk / NBW, bj = blk % NBW;
    const int tid = threadIdx.x;
    const int hh = tid / N;
    const int qi = tid - hh * N;
    const int h = hg * HPC + hh;

    for (int e = tid; e < (2 * P - 1) * 16; e += THREADS) {
        int rr = e >> 4, d = e & 15;
        rwT[d][rr] = relw[e];
        rhT[d][rr] = relh[e];
    }
    for (int e = tid; e < HPC * N * 4; e += THREADS) {
        int hl = e / (N * 4);
        int rem = e - hl * (N * 4);
        int key = rem >> 2, part = (rem & 3) << 2;
        int kr = key / P, kc = key - kr * P;
        int ktok = (bi * P + kr) * WW + bj * P + kc;
        size_t basek = (size_t)(b * NHEADS + hg * HPC + hl) * NTOK;
        *(float4*)&Ks[hl][key][part] = *(const float4*)&g_K[(basek + ktok) * HD + part];
        *(float4*)&Vs[hl][key][part] = *(const float4*)&g_V[(basek + ktok) * HD + part];
    }
    __syncthreads();
    for (int e = tid; e < HPC * P * 16; e += THREADS) {
        int hl = e / (P * 16);
        int rem = e - hl * (P * 16);
        int idx = rem >> 4, dd = rem & 15;
        float sc = 0.f, sr = 0.f;
#pragma unroll
        for (int k2 = 0; k2 < P; k2++) {
            sc += Vs[hl][k2 * P + idx][dd];
            sr += Vs[hl][idx * P + k2][dd];
        }
        Vc[hl][idx][dd] = sc;
        Vr[hl][idx][dd] = sr;
    }
    __syncthreads();

    const int r = qi / P, c = qi - (qi / P) * P;
    const int qtok = (bi * P + r) * WW + bj * P + c;     // spatial (for reading Q)
    const size_t base = (size_t)(b * NHEADS + h) * NTOK;
    float q[16];
    load16(&g_Q[(base + qtok) * HD], q);
    float o[16];
#pragma unroll
    for (int d = 0; d < 16; d++) o[d] = 0.f;
    float ssum = 0.f;

    for (int kk = 0; kk < N; kk++) {
        float kv[16];
        load16(&Ks[hh][kk][0], kv);
        float s = 0.f;
#pragma unroll
        for (int d = 0; d < 16; d++) s = fmaf(q[d], kv[d], s);
        float ew = __expf(s * ATTN_SCALE);
        ssum += ew;
        float vv[16];
        load16(&Vs[hh][kk][0], vv);
#pragma unroll
        for (int d = 0; d < 16; d++) o[d] = fmaf(ew, vv[d], o[d]);
    }
    float inv = 1.f / ssum;
#pragma unroll
    for (int d = 0; d < 16; d++) o[d] *= inv;

    const int cw = P - 1 - c, rw = P - 1 - r;
#pragma unroll 2
    for (int kc = 0; kc < P; kc++) {
        float w = 0.f, wh = 0.f;
#pragma unroll
        for (int d = 0; d < 16; d++) {
            w = fmaf(q[d], rwT[d][kc + cw], w);
            wh = fmaf(q[d], rhT[d][kc + rw], wh);
        }
        float vcv[16], vrv[16];
        load16(&Vc[hh][kc][0], vcv);
        load16(&Vr[hh][kc][0], vrv);
#pragma unroll
        for (int d = 0; d < 16; d++) {
            o[d] = fmaf(w, vcv[d], o[d]);
            o[d] = fmaf(wh, vrv[d], o[d]);
        }
    }
    // patch-major destination (flat reshape in reference)
    const int dtok = (bi * NBW + bj) * N + qi;
    float* dst = g_Osum + ((size_t)b * NTOK + dtok) * 128 + h * HD;
#pragma unroll
    for (int d4 = 0; d4 < 4; d4++) {
        float4 val = make_float4(o[4 * d4], o[4 * d4 + 1], o[4 * d4 + 2], o[4 * d4 + 3]);
        if (ACCUM) {
            float4 cur = *(float4*)&dst[4 * d4];
            val.x += cur.x; val.y += cur.y; val.z += cur.z; val.w += cur.w;
        }
        *(float4*)&dst[4 * d4] = val;
    }
}

// ---------------- attention for p=40 via mma.sync bf16 (flash style) ----------------
// 64 block-heads x 10 CTAs; CTA = 320 thr = 10 warps; warp = 16 queries.
// Softmax part in bf16 tensor cores (tiny vs fp32-exact rel-pos part -> safe).
__global__ __launch_bounds__(320) void attn40_kernel(
    const float* __restrict__ relw, const float* __restrict__ relh) {
    __shared__ __align__(16) uint32_t KsU[512];       // [64 keys][8 d-pairs] bf16x2
    __shared__ __align__(16) uint32_t VtU[16 * 36];   // [16 d][32 key-pairs], stride 36 u32
    __shared__ float Os[160][17];                     // softmax output (padded)
    __shared__ float rw[79 * 16], rh[79 * 16];        // rel tables [idx][d]
    __shared__ float Vc[40][16], Vr[40][16];

    const int bh = blockIdx.x / 10;
    const int qc = blockIdx.x - bh * 10;
    const int b = bh >> 5, blk = (bh >> 3) & 3, h = bh & 7;
    const int bi = blk >> 1, bj = blk & 1;
    const int tid = threadIdx.x;
    const size_t base = (size_t)(b * NHEADS + h) * NTOK;

    for (int e = tid; e < 79 * 16; e += 320) { rw[e] = relw[e]; rh[e] = relh[e]; }
    for (int e = tid; e < 640; e += 320) {
        ((float*)Vc)[e] = g_Vc40[bh * 640 + e];
        ((float*)Vr)[e] = g_Vr40[bh * 640 + e];
    }

    const int wid = tid >> 5, lane = tid & 31;
    const int lr = lane >> 2, lc = lane & 3;
    // ---- Q fragment (scaled by QK_SCALE; exact power-of-two * log2e const) ----
    uint32_t qa0, qa1, qa2, qa3;
    {
        int qia = qc * 160 + wid * 16 + lr;
        int qib = qia + 8;
        int ra = qia / 40, ca = qia - ra * 40;
        int rb = qib / 40, cb = qib - rb * 40;
        const float* qpa = &g_Q[(base + (bi * 40 + ra) * WW + bj * 40 + ca) * HD];
        const float* qpb = &g_Q[(base + (bi * 40 + rb) * WW + bj * 40 + cb) * HD];
        float2 f;
        f = *(const float2*)&qpa[2 * lc];     qa0 = bf16x2(f.x * QK_SCALE, f.y * QK_SCALE);
        f = *(const float2*)&qpb[2 * lc];     qa1 = bf16x2(f.x * QK_SCALE, f.y * QK_SCALE);
        f = *(const float2*)&qpa[2 * lc + 8]; qa2 = bf16x2(f.x * QK_SCALE, f.y * QK_SCALE);
        f = *(const float2*)&qpb[2 * lc + 8]; qa3 = bf16x2(f.x * QK_SCALE, f.y * QK_SCALE);
    }
    float oc0[4] = {0.f, 0.f, 0.f, 0.f};
    float oc1[4] = {0.f, 0.f, 0.f, 0.f};
    float rsum0 = 0.f, rsum1 = 0.f;

    for (int t = 0; t < 25; t++) {
        __syncthreads();
        // K tile: 64 keys x 16d as bf16x2
        for (int e = tid; e < 512; e += 320) {
            int key = e >> 3, dp = e & 7;
            int kidx = t * 64 + key;
            int kr = kidx / 40, kc2 = kidx - kr * 40;
            float2 f = *(const float2*)&g_K[(base + (bi * 40 + kr) * WW + bj * 40 + kc2) * HD + 2 * dp];
            KsU[e] = bf16x2(f.x, f.y);
        }
        // V tile transposed: VtU[d][key-pair]
        for (int e = tid; e < 512; e += 320) {
            int d = e >> 5, k2 = e & 31;
            int kidx = t * 64 + 2 * k2;            // even -> pair never crosses a row of 40
            int kr = kidx / 40, kc2 = kidx - kr * 40;
            size_t tok = base + (bi * 40 + kr) * WW + bj * 40 + kc2;
            float lo = g_V[tok * HD + d];
            float hi = g_V[(tok + 1) * HD + d];
            VtU[d * 36 + k2] = bf16x2(lo, hi);
        }
        __syncthreads();

        uint32_t p[8][2];
#pragma unroll
        for (int g = 0; g < 8; g++) {
            float c0 = 0.f, c1 = 0.f, c2 = 0.f, c3 = 0.f;
            uint32_t kb0 = KsU[(8 * g + lr) * 8 + lc];
            uint32_t kb1 = KsU[(8 * g + lr) * 8 + lc + 4];
            mma_bf16(c0, c1, c2, c3, qa0, qa1, qa2, qa3, kb0, kb1);
            float e0 = ex2f(c0), e1 = ex2f(c1), e2 = ex2f(c2), e3 = ex2f(c3);
            rsum0 += e0 + e1;
            rsum1 += e2 + e3;
            p[g][0] = bf16x2(e0, e1);
            p[g][1] = bf16x2(e2, e3);
        }
#pragma unroll
        for (int gp = 0; gp < 4; gp++) {
            uint32_t a0 = p[2 * gp][0], a1 = p[2 * gp][1];
            uint32_t a2 = p[2 * gp + 1][0], a3 = p[2 * gp + 1][1];
            uint32_t vb0 = VtU[lr * 36 + 8 * gp + lc];
            uint32_t vb1 = VtU[lr * 36 + 8 * gp + lc + 4];
            mma_bf16(oc0[0], oc0[1], oc0[2], oc0[3], a0, a1, a2, a3, vb0, vb1);
            vb0 = VtU[(8 + lr) * 36 + 8 * gp + lc];
            vb1 = VtU[(8 + lr) * 36 + 8 * gp + lc + 4];
            mma_bf16(oc1[0], oc1[1], oc1[2], oc1[3], a0, a1, a2, a3, vb0, vb1);
        }
    }
    // quad reduce row sums (lanes 4k..4k+3 share rows)
    rsum0 += __shfl_xor_sync(0xffffffffu, rsum0, 1);
    rsum0 += __shfl_xor_sync(0xffffffffu, rsum0, 2);
    rsum1 += __shfl_xor_sync(0xffffffffu, rsum1, 1);
    rsum1 += __shfl_xor_sync(0xffffffffu, rsum1, 2);
    float inv0 = 1.f / rsum0, inv1 = 1.f / rsum1;
    {
        int ql = wid * 16;
        Os[ql + lr][2 * lc]         = oc0[0] * inv0;
        Os[ql + lr][2 * lc + 1]     = oc0[1] * inv0;
        Os[ql + lr + 8][2 * lc]     = oc0[2] * inv1;
        Os[ql + lr + 8][2 * lc + 1] = oc0[3] * inv1;
        Os[ql + lr][2 * lc + 8]     = oc1[0] * inv0;
        Os[ql + lr][2 * lc + 9]     = oc1[1] * inv0;
        Os[ql + lr + 8][2 * lc + 8] = oc1[2] * inv1;
        Os[ql + lr + 8][2 * lc + 9] = oc1[3] * inv1;
    }
    __syncthreads();

    // ---- fp32 rel-pos epilogue: 2 threads per query (half=0 -> w, half=1 -> wh) ----
    const int qloc = tid >> 1, half = tid & 1;
    const int qi = qc * 160 + qloc;
    const int r = qi / 40, c = qi - r * 40;
    float q[16];
    load16(&g_Q[(base + (bi * 40 + r) * WW + bj * 40 + c) * HD], q);
    float o[8] = {0.f, 0.f, 0.f, 0.f, 0.f, 0.f, 0.f, 0.f};
    const int off = half ? (39 - r) : (39 - c);
    const float* tbl = half ? rh : rw;
#pragma unroll 2
    for (int kc = 0; kc < 40; kc++) {
        const float* tp = &tbl[(kc + off) * 16];
        float mine = 0.f;
#pragma unroll
        for (int d = 0; d < 16; d++) mine = fmaf(q[d], tp[d], mine);
        float other = __shfl_xor_sync(0xffffffffu, mine, 1);
        float w  = half ? other : mine;
        float wh = half ? mine  : other;
#pragma unroll
        for (int j = 0; j < 8; j++)
            o[j] = fmaf(w, Vc[kc][half * 8 + j], fmaf(wh, Vr[kc][half * 8 + j], o[j]));
    }
    const int pbase = (bi * 2 + bj) * 1600;
    float* dst = &g_Osum[((size_t)b * NTOK + pbase + qi) * 128 + h * HD + half * 8];
#pragma unroll
    for (int j4 = 0; j4 < 2; j4++) {
        float4 cur = *(float4*)&dst[4 * j4];
        cur.x += o[4 * j4 + 0] + Os[qloc][half * 8 + 4 * j4 + 0];
        cur.y += o[4 * j4 + 1] + Os[qloc][half * 8 + 4 * j4 + 1];
        cur.z += o[4 * j4 + 2] + Os[qloc][half * 8 + 4 * j4 + 2];
        cur.w += o[4 * j4 + 3] + Os[qloc][half * 8 + 4 * j4 + 3];
        *(float4*)&dst[4 * j4] = cur;
    }
}

// ---------------- final via bf16x3 mma: out = Osum(12800,128) @ Wc(128,128) + bc ----------------
// grid (100, 2), 256 threads (8 warps). Same structure as qkv_mma_kernel.
__global__ __launch_bounds__(256) void final_mma_kernel(float* __restrict__ out) {
    __shared__ uint32_t AsH[128][9], AsL[128][9];
    __shared__ uint32_t BsH[64][9], BsL[64][9];
    const int m0 = blockIdx.x * 128;
    const int n0 = blockIdx.y * 64;
    const int tid = threadIdx.x;
    const int wid = tid >> 5, lane = tid & 31;
    const int lr = lane >> 2, lc = lane & 3;
    float c[8][4];
#pragma unroll
    for (int j = 0; j < 8; j++)
#pragma unroll
        for (int i = 0; i < 4; i++) c[j][i] = 0.f;

    for (int kc = 0; kc < 8; kc++) {
        __syncthreads();
        {
            int row = tid >> 1, hf = tid & 1;
            const float* src = &g_Osum[(size_t)(m0 + row) * 128 + kc * 16 + hf * 8];
            float4 f0 = *(const float4*)src;
            float4 f1 = *(const float4*)(src + 4);
            uint32_t h, l;
            split_pair(f0.x, f0.y, h, l); AsH[row][hf * 4 + 0] = h; AsL[row][hf * 4 + 0] = l;
            split_pair(f0.z, f0.w, h, l); AsH[row][hf * 4 + 1] = h; AsL[row][hf * 4 + 1] = l;
            split_pair(f1.x, f1.y, h, l); AsH[row][hf * 4 + 2] = h; AsL[row][hf * 4 + 2] = l;
            split_pair(f1.z, f1.w, h, l); AsH[row][hf * 4 + 3] = h; AsL[row][hf * 4 + 3] = l;
        }
#pragma unroll
        for (int ee = 0; ee < 2; ee++) {
            int e = tid + ee * 256;
            int n = e & 63, kp = e >> 6;
            float b0 = g_Wc[(size_t)(kc * 16 + 2 * kp) * 128 + n0 + n];
            float b1 = g_Wc[(size_t)(kc * 16 + 2 * kp + 1) * 128 + n0 + n];
            uint32_t h, l; split_pair(b0, b1, h, l);
            BsH[n][kp] = h; BsL[n][kp] = l;
        }
        __syncthreads();
        const int rbase = wid * 16;
        uint32_t aH0 = AsH[rbase + lr][lc],     aH1 = AsH[rbase + lr + 8][lc];
        uint32_t aH2 = AsH[rbase + lr][lc + 4], aH3 = AsH[rbase + lr + 8][lc + 4];
        uint32_t aL0 = AsL[rbase + lr][lc],     aL1 = AsL[rbase + lr + 8][lc];
        uint32_t aL2 = AsL[rbase + lr][lc + 4], aL3 = AsL[rbase + lr + 8][lc + 4];
#pragma unroll
        for (int j = 0; j < 8; j++) {
            uint32_t bH0 = BsH[8 * j + lr][lc], bH1 = BsH[8 * j + lr][lc + 4];
            uint32_t bL0 = BsL[8 * j + lr][lc], bL1 = BsL[8 * j + lr][lc + 4];
            mma_bf16(c[j][0], c[j][1], c[j][2], c[j][3], aH0, aH1, aH2, aH3, bH0, bH1);
            mma_bf16(c[j][0], c[j][1], c[j][2], c[j][3], aL0, aL1, aL2, aL3, bH0, bH1);
            mma_bf16(c[j][0], c[j][1], c[j][2], c[j][3], aH0, aH1, aH2, aH3, bL0, bL1);
        }
    }
#pragma unroll
    for (int j = 0; j < 8; j++) {
        int ncol = n0 + 8 * j + 2 * lc;
        float b0v = g_bc[ncol], b1v = g_bc[ncol + 1];
        int t0 = m0 + wid * 16 + lr;
        *(float2*)&out[(size_t)t0 * 128 + ncol] = make_float2(c[j][0] + b0v, c[j][1] + b1v);
        *(float2*)&out[(size_t)(t0 + 8) * 128 + ncol] = make_float2(c[j][2] + b0v, c[j][3] + b1v);
    }
}

// ---------------- launcher ----------------
extern "C" void kernel_launch(void* const* d_in, const int* in_sizes, int n_in,
                              void* d_out, int out_size) {
    (void)in_sizes; (void)n_in; (void)out_size;
    const float* x      = (const float*)d_in[0];
    const float* wq     = (const float*)d_in[1];
    const float* wkv    = (const float*)d_in[2];
    const float* wproj  = (const float*)d_in[3];
    const float* bproj  = (const float*)d_in[4];
    const float* wfinal = (const float*)d_in[5];
    const float* bfinal = (const float*)d_in[6];
    const float* rw0 = (const float*)d_in[7];
    const float* rh0 = (const float*)d_in[8];
    const float* rw1 = (const float*)d_in[9];
    const float* rh1 = (const float*)d_in[10];
    const float* rw2 = (const float*)d_in[11];
    const float* rh2 = (const float*)d_in[12];
    float* out = (float*)d_out;

    qkv_mma_kernel<<<dim3(100, 6), 256>>>(x, wq, wkv);
    wc_kernel<<<128, 128>>>(wproj, wfinal, bproj, bfinal);
    vsum40_kernel<<<64, 640>>>();
    // p=4 STORES (initializes g_Osum: every (token,head) covered exactly once)
    attn_small_kernel<4, 8, false><<<800, 128>>>(rw0, rh0);
    attn_small_kernel<8, 2, true><<<800, 128>>>(rw1, rh1);
    attn40_kernel<<<640, 320>>>(rw2, rh2);
    final_mma_kernel<<<dim3(100, 2), 256>>>(out);
}